// round 11
// baseline (speedup 1.0000x reference)
#include <cuda_runtime.h>
#include <cuda_fp16.h>
#include <cstdint>

// ---------------------------------------------------------------- shapes
#define M_TOTAL 16384
#define D_DIM   4096
#define RANK    819
#define KPAD    832          // gemm2 K (rank padded to 64)
#define NPAD1   896          // Y columns padded (cols >=832 unused)
#define NACT1   832          // active N columns in gemm1

// ---------------------------------------------------------------- scratch
__device__ uint32_t g_Xh[(size_t)M_TOTAL * (D_DIM / 2)];   // x, [m][k-pair]
__device__ uint32_t g_Yh[(size_t)M_TOTAL * (NPAD1 / 2)];   // Y, [m][n-pair]
__device__ uint32_t g_B1[(size_t)(D_DIM / 2) * NPAD1];     // (U*S), [k-pair][n]
__device__ uint32_t g_B2[(size_t)(KPAD / 2) * D_DIM];      // V,     [k-pair][n]
__device__ int      g_flags[M_TOTAL / 256];                // Y 256-row blocks

// ---------------------------------------------------------------- helpers
static __device__ __forceinline__ uint32_t s2u(const void* p) {
    uint32_t a;
    asm("{ .reg .u64 t; cvta.to.shared.u64 t, %1; cvt.u32.u64 %0, t; }"
        : "=r"(a) : "l"(p));
    return a;
}
static __device__ __forceinline__ uint32_t pkh2(float x, float y) {
    __half2 h = __floats2half2_rn(x, y);
    return *reinterpret_cast<uint32_t*>(&h);
}
static __device__ __forceinline__ void cp16(uint32_t dst, const void* src) {
    asm volatile("cp.async.cg.shared.global [%0], [%1], 16;"
                 :: "r"(dst), "l"(src) : "memory");
}
#define CP_COMMIT() asm volatile("cp.async.commit_group;" ::: "memory")
#define CP_WAIT1()  asm volatile("cp.async.wait_group 1;" ::: "memory")

static __device__ __forceinline__ void mma16(float c[4],
                                             uint32_t a0, uint32_t a1,
                                             uint32_t a2, uint32_t a3,
                                             uint32_t b0, uint32_t b1) {
    asm volatile(
        "mma.sync.aligned.m16n8k16.row.col.f32.f16.f16.f32 "
        "{%0,%1,%2,%3}, {%4,%5,%6,%7}, {%8,%9}, {%0,%1,%2,%3};"
        : "+f"(c[0]), "+f"(c[1]), "+f"(c[2]), "+f"(c[3])
        : "r"(a0), "r"(a1), "r"(a2), "r"(a3), "r"(b0), "r"(b1));
}

// ---------------------------------------------------------------- merged prep
#define NX4 ((size_t)M_TOTAL * D_DIM / 4)
#define NB1 ((size_t)(D_DIM / 2) * NPAD1)
#define NB2 ((size_t)(KPAD / 2) * D_DIM)
#define NPREP (NX4 + NB1 + NB2)

__global__ void prep_all(const float4* __restrict__ X, uint2* __restrict__ Xh,
                         const float* __restrict__ U, const float* __restrict__ S,
                         uint32_t* __restrict__ B1,
                         const float* __restrict__ V, uint32_t* __restrict__ B2) {
    const size_t id = (size_t)blockIdx.x * blockDim.x + threadIdx.x;
    if (id < M_TOTAL / 256) g_flags[id] = 0;   // reset fusion flags (replay-safe)
    if (id < NX4) {
        float4 v = X[id];
        uint2 o;
        o.x = pkh2(v.x, v.y);
        o.y = pkh2(v.z, v.w);
        Xh[id] = o;
    } else if (id < NX4 + NB1) {
        const size_t i = id - NX4;
        const int n = (int)(i % NPAD1);
        const int kp = (int)(i / NPAD1);
        float v0 = 0.0f, v1 = 0.0f;
        if (n < RANK) {
            const float s = S[n];
            v0 = U[(size_t)(2 * kp) * RANK + n] * s;
            v1 = U[(size_t)(2 * kp + 1) * RANK + n] * s;
        }
        B1[i] = pkh2(v0, v1);
    } else {
        const size_t i = id - NX4 - NB1;
        const int n = (int)(i & (D_DIM - 1));
        const int kp = (int)(i >> 12);
        const int k0 = 2 * kp;
        float v0 = 0.0f, v1 = 0.0f;
        if (k0 < RANK)     v0 = V[(size_t)k0 * D_DIM + n];
        if (k0 + 1 < RANK) v1 = V[(size_t)(k0 + 1) * D_DIM + n];
        B2[i] = pkh2(v0, v1);
    }
}

// ---------------------------------------------------------------- GEMM body
// CTA tile BM x BN, 8 warps WM x (8/WM), warp tile 64x64, BK=64 halves.
// 3 smem stages, wait_group 1.  (R9-proven body, bm/bn passed in.)
#define BKW 32
#define STAGES 3

template <int BM, int BN, int WM, int KT, int LDAW, int LDBW,
          bool ROUND_OUT, bool ADD_X, bool MFAST, int NACT>
__device__ __forceinline__ void gemm_body(
    int bm, int bn,
    const uint32_t* __restrict__ Ag, const uint32_t* __restrict__ Bg,
    const uint32_t* __restrict__ Xh, const float* __restrict__ alphap,
    void* __restrict__ Og, int ldo)
{
    constexpr int ASTRIDE = BKW + 4;
    constexpr int BSTRIDE = BN + 8;
    constexpr int AW = BM * ASTRIDE;
    constexpr int BW = BKW * BSTRIDE;
    constexpr int SW = AW + BW;
    constexpr int ACH = BM * (BKW / 4);
    constexpr int BCH = BKW * (BN / 4);
    constexpr int WN = 8 / WM;
    constexpr int ACR = BKW / 4;
    constexpr int BCR = BN / 4;

    extern __shared__ __align__(128) uint32_t sm[];
    const int tid = threadIdx.x;
    const int lane = tid & 31, wid = tid >> 5;
    const int gid = lane >> 2, tg = lane & 3;
    const int warpM = MFAST ? (wid % WM) : (wid / WN);
    const int warpN = MFAST ? (wid / WM) : (wid % WN);
    const uint32_t smu = s2u(sm);

    const bool active = (bn + warpN * 64) < NACT;

    float alpha = 0.0f;
    if (ADD_X) alpha = *alphap;

    float c[4][8][4];
    #pragma unroll
    for (int i = 0; i < 4; i++)
        #pragma unroll
        for (int j = 0; j < 8; j++)
            #pragma unroll
            for (int v = 0; v < 4; v++) c[i][j][v] = 0.0f;

    #define LOADST(slot, kw0)                                                  \
    do {                                                                       \
        const uint32_t base = smu + (slot) * (SW * 4);                         \
        _Pragma("unroll")                                                      \
        for (int ii = 0; ii < (ACH + BCH) / 256; ii++) {                       \
            const int id = tid + 256 * ii;                                     \
            if (id < ACH) {                                                    \
                const int row = id / ACR, cc = id % ACR;                       \
                cp16(base + (row * ASTRIDE + cc * 4) * 4,                      \
                     Ag + (size_t)(bm + row) * LDAW + (kw0) + cc * 4);         \
            } else {                                                           \
                const int id2 = id - ACH;                                      \
                const int row = id2 / BCR, cc = id2 % BCR;                     \
                cp16(base + (AW + row * BSTRIDE + cc * 4) * 4,                 \
                     Bg + (size_t)((kw0) + row) * LDBW + bn + cc * 4);         \
            }                                                                  \
        }                                                                      \
    } while (0)

    LOADST(0, 0);    CP_COMMIT();
    LOADST(1, BKW);  CP_COMMIT();

    int slot = 0;
    for (int t = 0; t < KT; t++) {
        CP_WAIT1();
        __syncthreads();
        if (t + 2 < KT) {
            const int ns = (slot + 2 >= STAGES) ? slot + 2 - STAGES : slot + 2;
            LOADST(ns, (t + 2) * BKW);
        }
        CP_COMMIT();

        if (active) {
            const uint32_t* As = sm + slot * SW;
            const uint32_t* Bs = As + AW;

            uint32_t af[2][4][4];
            #pragma unroll
            for (int i = 0; i < 4; i++) {
                const int r0 = warpM * 64 + i * 16 + gid;
                af[0][i][0] = As[r0 * ASTRIDE + tg];
                af[0][i][1] = As[(r0 + 8) * ASTRIDE + tg];
                af[0][i][2] = As[r0 * ASTRIDE + tg + 4];
                af[0][i][3] = As[(r0 + 8) * ASTRIDE + tg + 4];
            }
            #pragma unroll
            for (int ks = 0; ks < 4; ks++) {
                const int cur = ks & 1, nxt = cur ^ 1;
                if (ks < 3) {
                    const int cbw = (ks + 1) * 8;
                    #pragma unroll
                    for (int i = 0; i < 4; i++) {
                        const int r0 = warpM * 64 + i * 16 + gid;
                        af[nxt][i][0] = As[r0 * ASTRIDE + cbw + tg];
                        af[nxt][i][1] = As[(r0 + 8) * ASTRIDE + cbw + tg];
                        af[nxt][i][2] = As[r0 * ASTRIDE + cbw + tg + 4];
                        af[nxt][i][3] = As[(r0 + 8) * ASTRIDE + cbw + tg + 4];
                    }
                }
                const int kp0 = ks * 8;
                #pragma unroll
                for (int j = 0; j < 8; j++) {
                    const int col = warpN * 64 + j * 8 + gid;
                    const uint32_t b0 = Bs[(kp0 + tg) * BSTRIDE + col];
                    const uint32_t b1 = Bs[(kp0 + 4 + tg) * BSTRIDE + col];
                    #pragma unroll
                    for (int i = 0; i < 4; i++)
                        mma16(c[i][j], af[cur][i][0], af[cur][i][1],
                              af[cur][i][2], af[cur][i][3], b0, b1);
                }
            }
        }
        slot = (slot + 1 >= STAGES) ? 0 : slot + 1;
    }
    #undef LOADST

    if (!active) return;

    if (ROUND_OUT) {
        uint32_t* Yw = reinterpret_cast<uint32_t*>(Og);
        #pragma unroll
        for (int i = 0; i < 4; i++) {
            const int r0 = bm + warpM * 64 + i * 16 + gid;
            #pragma unroll
            for (int j = 0; j < 8; j++) {
                const int n0 = bn + warpN * 64 + j * 8 + tg * 2;
                Yw[(size_t)r0 * ldo + (n0 >> 1)]       = pkh2(c[i][j][0], c[i][j][1]);
                Yw[(size_t)(r0 + 8) * ldo + (n0 >> 1)] = pkh2(c[i][j][2], c[i][j][3]);
            }
        }
    } else {
        float* Of = reinterpret_cast<float*>(Og);
        #pragma unroll
        for (int i = 0; i < 4; i++) {
            const int r0 = bm + warpM * 64 + i * 16 + gid;
            #pragma unroll
            for (int j = 0; j < 8; j++) {
                const int n0 = bn + warpN * 64 + j * 8 + tg * 2;
                #pragma unroll
                for (int h = 0; h < 2; h++) {
                    const size_t off = (size_t)(r0 + 8 * h) * ldo + n0;
                    const uint32_t xw =
                        Xh[(size_t)(r0 + 8 * h) * (D_DIM / 2) + (n0 >> 1)];
                    const float2 xv =
                        __half22float2(*reinterpret_cast<const __half2*>(&xw));
                    float2 ov;
                    ov.x = fmaf(alpha, xv.x, c[i][j][2 * h + 0]);
                    ov.y = fmaf(alpha, xv.y, c[i][j][2 * h + 1]);
                    *reinterpret_cast<float2*>(Of + off) = ov;
                }
            }
        }
    }
}

// ---------------------------------------------------------------- fused GEMM
// bids [0,448): gemm1 tiles (bn fastest, 7 per 256-row block).
// bids [448, 2496): gemm2 tiles (bn fastest -> low bm first), spin on flag.
#define G1_TILES 448
#define G2_TILES 2048
// smem: max(gemm1 stage, gemm2 stage) * 3
#define FUSED_SMEM (STAGES * (256 * 36 + 32 * 136) * 4)   // 162816 >= gemm2's 156672

__global__ __launch_bounds__(256, 1)
void gemm_fused(const uint32_t* __restrict__ Xh, const uint32_t* __restrict__ B1,
                const uint32_t* __restrict__ B2, uint32_t* __restrict__ Yw,
                const float* __restrict__ alphap, float* __restrict__ Out) {
    const int bid = blockIdx.x;
    if (bid < G1_TILES) {
        // ---- GEMM1: Yh[bm:bm+256][bn:bn+128] = Xh @ B1
        const int bn = (bid % 7) * 128;
        const int bm = (bid / 7) * 256;
        gemm_body<256, 128, 4, D_DIM / 64, D_DIM / 2, NPAD1, true, false,
                  true, NACT1>(bm, bn, Xh, B1, nullptr, nullptr, Yw, NPAD1 / 2);
        __threadfence();
        __syncthreads();
        if (threadIdx.x == 0) atomicAdd(&g_flags[bm >> 8], 1);
    } else {
        // ---- GEMM2: Out[bm:bm+128][bn:bn+256] = Yh @ B2 + alpha*Xh
        const int idx = bid - G1_TILES;
        const int bn = (idx & 15) * 256;
        const int bm = (idx >> 4) * 128;
        if (threadIdx.x == 0) {
            while (*(volatile int*)&g_flags[bm >> 8] < 7) { }
        }
        __syncthreads();
        gemm_body<128, 256, 2, KPAD / 64, NPAD1 / 2, D_DIM, false, true,
                  false, (1 << 30)>(bm, bn, Yw, B2, Xh, alphap, Out, D_DIM);
    }
}

// ---------------------------------------------------------------- launch
extern "C" void kernel_launch(void* const* d_in, const int* in_sizes, int n_in,
                              void* d_out, int out_size) {
    const float* x     = (const float*)d_in[0];
    const float* U     = (const float*)d_in[1];
    const float* S     = (const float*)d_in[2];
    const float* V     = (const float*)d_in[3];
    const float* alpha = (const float*)d_in[4];
    float* out = (float*)d_out;

    uint32_t *Xhp, *Yhp, *B1p, *B2p;
    cudaGetSymbolAddress((void**)&Xhp, g_Xh);
    cudaGetSymbolAddress((void**)&Yhp, g_Yh);
    cudaGetSymbolAddress((void**)&B1p, g_B1);
    cudaGetSymbolAddress((void**)&B2p, g_B2);

    cudaFuncSetAttribute(gemm_fused, cudaFuncAttributeMaxDynamicSharedMemorySize,
                         FUSED_SMEM);

    prep_all<<<(unsigned)(NPREP / 256), 256>>>((const float4*)x, (uint2*)Xhp,
                                               U, S, B1p, V, B2p);

    gemm_fused<<<G1_TILES + G2_TILES, 256, FUSED_SMEM>>>(Xhp, B1p, B2p, Yhp,
                                                         alpha, out);
}

// round 12
// speedup vs baseline: 1.1806x; 1.1806x over previous
#include <cuda_runtime.h>
#include <cuda_fp16.h>
#include <cstdint>

// ---------------------------------------------------------------- shapes
#define M_TOTAL 16384
#define D_DIM   4096
#define RANK    819
#define KPAD    832          // gemm2 K (rank padded to 64)
#define NPAD1   896          // Y columns padded (cols >=832 unused)
#define NACT1   832          // active N columns in gemm1

// ---------------------------------------------------------------- scratch
__device__ uint32_t g_Xh[(size_t)M_TOTAL * (D_DIM / 2)];   // x, [m][k-pair]
__device__ uint32_t g_Yh[(size_t)M_TOTAL * (NPAD1 / 2)];   // Y, [m][n-pair]
__device__ uint32_t g_B1[(size_t)(D_DIM / 2) * NPAD1];     // (U*S), [k-pair][n]
__device__ uint32_t g_B2[(size_t)(KPAD / 2) * D_DIM];      // V,     [k-pair][n]

// ---------------------------------------------------------------- helpers
static __device__ __forceinline__ uint32_t s2u(const void* p) {
    uint32_t a;
    asm("{ .reg .u64 t; cvta.to.shared.u64 t, %1; cvt.u32.u64 %0, t; }"
        : "=r"(a) : "l"(p));
    return a;
}
static __device__ __forceinline__ uint32_t pkh2(float x, float y) {
    __half2 h = __floats2half2_rn(x, y);
    return *reinterpret_cast<uint32_t*>(&h);
}
static __device__ __forceinline__ void cp16(uint32_t dst, const void* src) {
    asm volatile("cp.async.cg.shared.global [%0], [%1], 16;"
                 :: "r"(dst), "l"(src) : "memory");
}
#define CP_COMMIT() asm volatile("cp.async.commit_group;" ::: "memory")
#define CP_WAIT1()  asm volatile("cp.async.wait_group 1;" ::: "memory")

static __device__ __forceinline__ void mma16(float c[4],
                                             uint32_t a0, uint32_t a1,
                                             uint32_t a2, uint32_t a3,
                                             uint32_t b0, uint32_t b1) {
    asm volatile(
        "mma.sync.aligned.m16n8k16.row.col.f32.f16.f16.f32 "
        "{%0,%1,%2,%3}, {%4,%5,%6,%7}, {%8,%9}, {%0,%1,%2,%3};"
        : "+f"(c[0]), "+f"(c[1]), "+f"(c[2]), "+f"(c[3])
        : "r"(a0), "r"(a1), "r"(a2), "r"(a3), "r"(b0), "r"(b1));
}

// ---------------------------------------------------------------- merged prep
#define NX4 ((size_t)M_TOTAL * D_DIM / 4)
#define NB1 ((size_t)(D_DIM / 2) * NPAD1)
#define NB2 ((size_t)(KPAD / 2) * D_DIM)
#define NPREP (NX4 + NB1 + NB2)

__global__ void prep_all(const float4* __restrict__ X, uint2* __restrict__ Xh,
                         const float* __restrict__ U, const float* __restrict__ S,
                         uint32_t* __restrict__ B1,
                         const float* __restrict__ V, uint32_t* __restrict__ B2) {
    const size_t id = (size_t)blockIdx.x * blockDim.x + threadIdx.x;
    if (id < NX4) {
        float4 v = X[id];
        uint2 o;
        o.x = pkh2(v.x, v.y);
        o.y = pkh2(v.z, v.w);
        Xh[id] = o;
    } else if (id < NX4 + NB1) {
        const size_t i = id - NX4;
        const int n = (int)(i % NPAD1);
        const int kp = (int)(i / NPAD1);
        float v0 = 0.0f, v1 = 0.0f;
        if (n < RANK) {
            const float s = S[n];
            v0 = U[(size_t)(2 * kp) * RANK + n] * s;
            v1 = U[(size_t)(2 * kp + 1) * RANK + n] * s;
        }
        B1[i] = pkh2(v0, v1);
    } else {
        const size_t i = id - NX4 - NB1;
        const int n = (int)(i & (D_DIM - 1));
        const int kp = (int)(i >> 12);
        const int k0 = 2 * kp;
        float v0 = 0.0f, v1 = 0.0f;
        if (k0 < RANK)     v0 = V[(size_t)k0 * D_DIM + n];
        if (k0 + 1 < RANK) v1 = V[(size_t)(k0 + 1) * D_DIM + n];
        B2[i] = pkh2(v0, v1);
    }
}

// ---------------------------------------------------------------- GEMM body
// CTA tile 128x128, 4 warps (WM=2 x WN=2), warp tile 64x64, 128 threads.
// K tile = 64 halves = 32 words. 3 smem stages (35840 B each), occupancy 2.
#define BKW 32
#define STAGES 3
#define NT 128                            // threads per CTA

// smem per stage: A 128*36 + B 32*136 = 8960 words = 35840 B (both GEMMs)
#define ASTRIDE 36
#define BSTRIDE 136
#define AW (128 * ASTRIDE)                // 4608 words
#define BW (BKW * BSTRIDE)                // 4352 words
#define SW (AW + BW)                      // 8960 words
#define SMEM_B (STAGES * SW * 4)          // 107520 B

template <int KT, int LDAW, int LDBW, bool ROUND_OUT, bool ADD_X,
          bool MFAST, int NACT>
__device__ __forceinline__ void gemm_body(
    int bm, int bn,
    const uint32_t* __restrict__ Ag, const uint32_t* __restrict__ Bg,
    const uint32_t* __restrict__ Xh, const float* __restrict__ alphap,
    void* __restrict__ Og, int ldo)
{
    extern __shared__ __align__(128) uint32_t sm[];
    const int tid = threadIdx.x;
    const int lane = tid & 31, wid = tid >> 5;   // wid 0..3
    const int gid = lane >> 2, tg = lane & 3;
    const int warpM = MFAST ? (wid & 1) : (wid >> 1);
    const int warpN = MFAST ? (wid >> 1) : (wid & 1);
    const uint32_t smu = s2u(sm);

    const bool active = (bn + warpN * 64) < NACT;

    float alpha = 0.0f;
    if (ADD_X) alpha = *alphap;

    float c[4][8][4];
    #pragma unroll
    for (int i = 0; i < 4; i++)
        #pragma unroll
        for (int j = 0; j < 8; j++)
            #pragma unroll
            for (int v = 0; v < 4; v++) c[i][j][v] = 0.0f;

    // 2048 16B chunks per stage (1024 A + 1024 B), 16 per thread
    #define LOADST(slot, kw0)                                                  \
    do {                                                                       \
        const uint32_t base = smu + (slot) * (SW * 4);                         \
        _Pragma("unroll")                                                      \
        for (int ii = 0; ii < 16; ii++) {                                      \
            const int id = tid + NT * ii;                                      \
            if (id < 1024) {                                                   \
                const int row = id >> 3, cc = id & 7;                          \
                cp16(base + (row * ASTRIDE + cc * 4) * 4,                      \
                     Ag + (size_t)(bm + row) * LDAW + (kw0) + cc * 4);         \
            } else {                                                           \
                const int id2 = id - 1024;                                     \
                const int row = id2 >> 5, cc = id2 & 31;                       \
                cp16(base + (AW + row * BSTRIDE + cc * 4) * 4,                 \
                     Bg + (size_t)((kw0) + row) * LDBW + bn + cc * 4);         \
            }                                                                  \
        }                                                                      \
    } while (0)

    LOADST(0, 0);    CP_COMMIT();
    LOADST(1, BKW);  CP_COMMIT();

    int slot = 0;
    for (int t = 0; t < KT; t++) {
        CP_WAIT1();
        __syncthreads();
        if (t + 2 < KT) {
            const int ns = (slot + 2 >= STAGES) ? slot + 2 - STAGES : slot + 2;
            LOADST(ns, (t + 2) * BKW);
        }
        CP_COMMIT();

        if (active) {
            const uint32_t* As = sm + slot * SW;
            const uint32_t* Bs = As + AW;

            uint32_t af[2][4][4];
            #pragma unroll
            for (int i = 0; i < 4; i++) {
                const int r0 = warpM * 64 + i * 16 + gid;
                af[0][i][0] = As[r0 * ASTRIDE + tg];
                af[0][i][1] = As[(r0 + 8) * ASTRIDE + tg];
                af[0][i][2] = As[r0 * ASTRIDE + tg + 4];
                af[0][i][3] = As[(r0 + 8) * ASTRIDE + tg + 4];
            }
            #pragma unroll
            for (int ks = 0; ks < 4; ks++) {
                const int cur = ks & 1, nxt = cur ^ 1;
                if (ks < 3) {
                    const int cbw = (ks + 1) * 8;
                    #pragma unroll
                    for (int i = 0; i < 4; i++) {
                        const int r0 = warpM * 64 + i * 16 + gid;
                        af[nxt][i][0] = As[r0 * ASTRIDE + cbw + tg];
                        af[nxt][i][1] = As[(r0 + 8) * ASTRIDE + cbw + tg];
                        af[nxt][i][2] = As[r0 * ASTRIDE + cbw + tg + 4];
                        af[nxt][i][3] = As[(r0 + 8) * ASTRIDE + cbw + tg + 4];
                    }
                }
                const int kp0 = ks * 8;
                #pragma unroll
                for (int j = 0; j < 8; j++) {
                    const int col = warpN * 64 + j * 8 + gid;
                    const uint32_t b0 = Bs[(kp0 + tg) * BSTRIDE + col];
                    const uint32_t b1 = Bs[(kp0 + 4 + tg) * BSTRIDE + col];
                    #pragma unroll
                    for (int i = 0; i < 4; i++)
                        mma16(c[i][j], af[cur][i][0], af[cur][i][1],
                              af[cur][i][2], af[cur][i][3], b0, b1);
                }
            }
        }
        slot = (slot + 1 >= STAGES) ? 0 : slot + 1;
    }
    #undef LOADST

    if (!active) return;

    if (ROUND_OUT) {
        uint32_t* Yw = reinterpret_cast<uint32_t*>(Og);
        #pragma unroll
        for (int i = 0; i < 4; i++) {
            const int r0 = bm + warpM * 64 + i * 16 + gid;
            #pragma unroll
            for (int j = 0; j < 8; j++) {
                const int n0 = bn + warpN * 64 + j * 8 + tg * 2;
                Yw[(size_t)r0 * ldo + (n0 >> 1)]       = pkh2(c[i][j][0], c[i][j][1]);
                Yw[(size_t)(r0 + 8) * ldo + (n0 >> 1)] = pkh2(c[i][j][2], c[i][j][3]);
            }
        }
    } else {
        float* Of = reinterpret_cast<float*>(Og);
        #pragma unroll
        for (int i = 0; i < 4; i++) {
            const int r0 = bm + warpM * 64 + i * 16 + gid;
            #pragma unroll
            for (int j = 0; j < 8; j++) {
                const int n0 = bn + warpN * 64 + j * 8 + tg * 2;
                #pragma unroll
                for (int h = 0; h < 2; h++) {
                    const size_t off = (size_t)(r0 + 8 * h) * ldo + n0;
                    const uint32_t xw =
                        Xh[(size_t)(r0 + 8 * h) * (D_DIM / 2) + (n0 >> 1)];
                    const float2 xv =
                        __half22float2(*reinterpret_cast<const __half2*>(&xw));
                    float2 ov;
                    ov.x = fmaf(alpha, xv.x, c[i][j][2 * h + 0]);
                    ov.y = fmaf(alpha, xv.y, c[i][j][2 * h + 1]);
                    *reinterpret_cast<float2*>(Of + off) = ov;
                }
            }
        }
    }
}

// GEMM1: Yh[16384][896] = Xh @ B1.  CTA 128x128, grid 7x128=896, occ 2.
// MFAST: warpN spread so the inactive edge pair frees distinct SMSPs.
__global__ __launch_bounds__(NT, 2)
void gemm1(const uint32_t* __restrict__ Xh, const uint32_t* __restrict__ B1,
           uint32_t* __restrict__ Yw) {
    gemm_body<D_DIM / 64, D_DIM / 2, NPAD1, true, false, true, NACT1>(
        blockIdx.y * 128, blockIdx.x * 128, Xh, B1, nullptr, nullptr,
        Yw, NPAD1 / 2);
}

// GEMM2: Out = Yh[:, :832] @ B2 + alpha * Xh.  CTA 128x128, grid 32x128, occ 2.
__global__ __launch_bounds__(NT, 2)
void gemm2(const uint32_t* __restrict__ Yh, const uint32_t* __restrict__ B2,
           const uint32_t* __restrict__ Xh, const float* __restrict__ alphap,
           float* __restrict__ Out) {
    gemm_body<KPAD / 64, NPAD1 / 2, D_DIM, false, true, false, (1 << 30)>(
        blockIdx.y * 128, blockIdx.x * 128, Yh, B2, Xh, alphap, Out, D_DIM);
}

// ---------------------------------------------------------------- launch
extern "C" void kernel_launch(void* const* d_in, const int* in_sizes, int n_in,
                              void* d_out, int out_size) {
    const float* x     = (const float*)d_in[0];
    const float* U     = (const float*)d_in[1];
    const float* S     = (const float*)d_in[2];
    const float* V     = (const float*)d_in[3];
    const float* alpha = (const float*)d_in[4];
    float* out = (float*)d_out;

    uint32_t *Xhp, *Yhp, *B1p, *B2p;
    cudaGetSymbolAddress((void**)&Xhp, g_Xh);
    cudaGetSymbolAddress((void**)&Yhp, g_Yh);
    cudaGetSymbolAddress((void**)&B1p, g_B1);
    cudaGetSymbolAddress((void**)&B2p, g_B2);

    cudaFuncSetAttribute(gemm1, cudaFuncAttributeMaxDynamicSharedMemorySize,
                         SMEM_B);
    cudaFuncSetAttribute(gemm2, cudaFuncAttributeMaxDynamicSharedMemorySize,
                         SMEM_B);

    prep_all<<<(unsigned)(NPREP / 256), 256>>>((const float4*)x, (uint2*)Xhp,
                                               U, S, B1p, V, B2p);

    gemm1<<<dim3(NPAD1 / 128, M_TOTAL / 128), NT, SMEM_B>>>(Xhp, B1p, Yhp);
    gemm2<<<dim3(D_DIM / 128, M_TOTAL / 128), NT, SMEM_B>>>(Yhp, B2p, Xhp,
                                                            alpha, out);
}